// round 12
// baseline (speedup 1.0000x reference)
#include <cuda_runtime.h>

#define SEG    96                 // samples per lane
#define WSPAN  (32 * SEG)         // 3072-sample warp span
#define WOUT   (WSPAN / 2)        // 1536 output samples (lanes 16..31)
#define WARPS  4
#define BLOCK  (WARPS * 32)       // 128
#define COUT   (WARPS * WOUT)     // 6144 outputs per CTA

__device__ __forceinline__ void get_params(const float* __restrict__ p,
                                           float& c1, float& c2,
                                           float& attack, float& decay, float& gain) {
    attack = fmaxf(p[0], 1e-7f);
    decay  = fmaxf(p[1], 1e-7f);
    c1 = fminf(fmaxf(p[2], 1e-7f), 0.99f);   // lowpass
    c2 = fminf(fmaxf(p[3], 1e-7f), 0.99f);   // highpass
    gain = fmaxf(p[4], 1e-7f);
}

__device__ __forceinline__ void mat_sq(float& m00, float& m10, float& m11) {
    float n00 = m00 * m00;
    float n10 = m10 * (m00 + m11);
    float n11 = m11 * m11;
    m00 = n00; m10 = n10; m11 = n11;
}

// ---------------------------------------------------------------------------
// Warp-autonomous kernel: each warp covers [out_base-1536, out_base+1536).
// Lanes sweep SEG samples zero-state; KS scan (shuffles only) gives each lane
// its exclusive seed; lanes 16..31 replay their segment with envelope + store.
// No shared memory, no __syncthreads, no inter-CTA communication.
// ---------------------------------------------------------------------------
__global__ void __launch_bounds__(BLOCK, 8)
ng_warp(const float* __restrict__ params, const float* __restrict__ x,
        float* __restrict__ out, int n) {
    float c1, c2, at, de, g;
    get_params(params, c1, c2, at, de, g);
    const float b1 = 1.0f - c1;
    const float dcoef = c2 * (c1 - 1.0f);
    const float bb = c2 * b1;

    const int tid  = threadIdx.x;
    const int lane = tid & 31;
    const int w    = tid >> 5;

    const long out_base  = (long)blockIdx.x * COUT + (long)w * WOUT;
    const long span_base = out_base - (long)WOUT;          // may be negative (first warp)
    const long lbase     = span_base + (long)lane * SEG;   // this lane's segment start

    // ---- stride-4 zero-state sweep over SEG samples ----
    const float A2_00 = c1 * c1, A2_10 = dcoef * (c1 + c2), A2_11 = c2 * c2;
    const float A4_00 = A2_00 * A2_00, A4_10 = A2_10 * (A2_00 + A2_11), A4_11 = A2_11 * A2_11;
    const float q0x = b1,       q0y = bb;
    const float q1x = c1 * q0x, q1y = fmaf(dcoef, q0x, c2 * q0y);
    const float q2x = c1 * q1x, q2y = fmaf(dcoef, q1x, c2 * q1y);
    const float q3x = c1 * q2x, q3y = fmaf(dcoef, q2x, c2 * q2y);

    float v0 = 0.0f, v1 = 0.0f;
    if (lbase >= 0 && lbase + SEG <= n) {
        const float4* xp = (const float4*)(x + lbase);
        float4 q = xp[0];
        #pragma unroll
        for (int k = 0; k < SEG / 4; k++) {
            float4 qn;
            if (k + 1 < SEG / 4) qn = xp[k + 1];
            float u0 = fmaf(q2x, q.y, q3x * q.x) + fmaf(q0x, q.w, q1x * q.z);
            float u1 = fmaf(q2y, q.y, q3y * q.x) + fmaf(q0y, q.w, q1y * q.z);
            float v0n = fmaf(A4_00, v0, u0);
            v1 = fmaf(A4_10, v0, fmaf(A4_11, v1, u1));
            v0 = v0n;
            q = qn;
        }
    } else if (lbase + SEG > 0 && lbase < n) {
        // boundary segment (global start or tail): serial masked
        #pragma unroll 4
        for (int j = 0; j < SEG; j++) {
            long idx = lbase + j;
            float xn = (idx >= 0 && idx < n) ? x[idx] : 0.0f;
            float t  = fmaf(dcoef, v0, bb * xn);
            v1 = fmaf(c2, v1, t);
            v0 = fmaf(c1, v0, b1 * xn);
        }
    } // else fully out of range: state stays zero

    // ---- P = A^SEG = A^96 = A^32 * A^64 ----
    float pk00 = c1, pk10 = dcoef, pk11 = c2;
    #pragma unroll
    for (int k = 0; k < 5; k++) mat_sq(pk00, pk10, pk11);   // A^32
    {
        float s00 = pk00, s10 = pk10, s11 = pk11;           // A^32
        mat_sq(s00, s10, s11);                              // A^64
        float t00 = pk00 * s00;
        float t10 = fmaf(pk10, s00, pk11 * s10);
        float t11 = pk11 * s11;
        pk00 = t00; pk10 = t10; pk11 = t11;                 // A^96
    }

    // ---- vector-only KS scan with constant round matrices P^(2^k) ----
    #pragma unroll
    for (int k = 0; k < 5; k++) {
        int dd = 1 << k;
        float o0 = __shfl_up_sync(0xffffffffu, v0, dd);
        float o1 = __shfl_up_sync(0xffffffffu, v1, dd);
        if (lane >= dd) {
            v0 = fmaf(pk00, o0, v0);
            v1 = fmaf(pk10, o0, fmaf(pk11, o1, v1));
        }
        mat_sq(pk00, pk10, pk11);
    }

    // exclusive seed for this lane's segment
    float s0 = __shfl_up_sync(0xffffffffu, v0, 1);
    float s1 = __shfl_up_sync(0xffffffffu, v1, 1);
    if (lane == 0) { s0 = 0.0f; s1 = 0.0f; }

    // ---- output lanes: replay segment with envelope, store ----
    if (lane >= 16 && lbase < n) {
        float y1 = s0, y2 = s1;

        const float inv_n1 = 1.0f / (float)(n - 1);
        const float k1 = 1.0f / de;
        const float k2 = 1.0f / at + k1;
        const float t0 = (float)lbase * inv_n1;
        float e1 = g * __expf(-t0 * k1);
        float e2 = g * __expf(-t0 * k2);
        const float r1c = __expf(-inv_n1 * k1);
        const float r2c = __expf(-inv_n1 * k2);
        const float r1s = r1c * r1c;
        const float r2s = r2c * r2c;

        // stride-2 replay constants
        const float Ab0 = c1 * b1;
        const float Ab1 = fmaf(dcoef, b1, c2 * bb);

        if (lbase + SEG <= n) {
            const float4* xp = (const float4*)(x + lbase);   // L1-resident (just swept)
            float4* op = (float4*)(out + lbase);
            #pragma unroll 4
            for (int k = 0; k < SEG / 4; k++) {
                float4 q = xp[k];
                float o[4];
                #pragma unroll
                for (int pr = 0; pr < 2; pr++) {
                    float xa = (pr == 0) ? q.x : q.z;
                    float xb = (pr == 0) ? q.y : q.w;
                    // mid state after xa (off critical chain)
                    float y2m = fmaf(dcoef, y1, fmaf(c2, y2, bb * xa));
                    // pair update
                    float u0 = fmaf(Ab0, xa, b1 * xb);
                    float u1 = fmaf(Ab1, xa, bb * xb);
                    float y1n = fmaf(A2_00, y1, u0);
                    y2 = fmaf(A2_10, y1, fmaf(A2_11, y2, u1));
                    y1 = y1n;
                    float ea = e1 - e2;
                    float eb = fmaf(e1, r1c, -(e2 * r2c));
                    e1 *= r1s; e2 *= r2s;
                    o[2*pr]     = y2m * ea;
                    o[2*pr + 1] = y2  * eb;
                }
                float4 ov; ov.x = o[0]; ov.y = o[1]; ov.z = o[2]; ov.w = o[3];
                __stcs(&op[k], ov);
            }
        } else {
            // tail: serial masked
            #pragma unroll 4
            for (int j = 0; j < SEG; j++) {
                long idx = lbase + j;
                if (idx >= n) break;
                float xn = x[idx];
                float t  = fmaf(dcoef, y1, bb * xn);
                y2 = fmaf(c2, y2, t);
                y1 = fmaf(c1, y1, b1 * xn);
                float val = y2 * (e1 - e2);
                e1 *= r1c; e2 *= r2c;
                out[idx] = val;
            }
        }
    }
}

// ---------------------------------------------------------------------------
extern "C" void kernel_launch(void* const* d_in, const int* in_sizes, int n_in,
                              void* d_out, int out_size) {
    int i_par = 0, i_noise = 1;
    if (n_in >= 2 && in_sizes[0] > in_sizes[1]) { i_par = 1; i_noise = 0; }
    const float* params = (const float*)d_in[i_par];
    const float* noise  = (const float*)d_in[i_noise];
    float* out = (float*)d_out;
    const int n = in_sizes[i_noise];
    const int G = (n + COUT - 1) / COUT;   // n = 2^22 -> G = 683

    ng_warp<<<G, BLOCK>>>(params, noise, out, n);
}

// round 13
// speedup vs baseline: 1.5664x; 1.5664x over previous
#include <cuda_runtime.h>

#define ITEMS 28
#define BLOCK 256
#define CHUNK (ITEMS * BLOCK)    // 7168 -> G=586
#define NWARP (BLOCK / 32)       // 8
#define MAXBLKS 1024

// correction kernel geometry
#define FIXN   1536              // correct first 1536 samples of each block (0.99^1536 ~ 2e-7)
#define FITEMS 8
#define FBLOCK (FIXN / FITEMS)   // 192 threads
#define FNWARP (FBLOCK / 32)     // 6

__device__ float2 g_agg[MAXBLKS];   // per-block zero-state end state

__device__ __forceinline__ void get_params(const float* __restrict__ p,
                                           float& c1, float& c2,
                                           float& attack, float& decay, float& gain) {
    attack = fmaxf(p[0], 1e-7f);
    decay  = fmaxf(p[1], 1e-7f);
    c1 = fminf(fmaxf(p[2], 1e-7f), 0.99f);   // lowpass
    c2 = fminf(fmaxf(p[3], 1e-7f), 0.99f);   // highpass
    gain = fmaxf(p[4], 1e-7f);
}

__device__ __forceinline__ void mat_mul(float& c00, float& c10, float& c11,
                                        float a00, float a10, float a11,
                                        float b00, float b10, float b11) {
    c00 = a00 * b00;
    c10 = fmaf(a10, b00, a11 * b10);
    c11 = a11 * b11;
}

__device__ __forceinline__ void mat_sq(float& m00, float& m10, float& m11) {
    float n00 = m00 * m00;
    float n10 = m10 * (m00 + m11);
    float n11 = m11 * m11;
    m00 = n00; m10 = n10; m11 = n11;
}

// P = A^28 (binary 11100): 5 squarings + 3 muls
__device__ __forceinline__ void mat_pow28(float a00, float a10, float a11,
                                          float& M00, float& M10, float& M11) {
    M00 = 1.0f; M10 = 0.0f; M11 = 1.0f;
    float p00 = a00, p10 = a10, p11 = a11;
    #pragma unroll
    for (int b = 0; b < 5; b++) {
        if ((28 >> b) & 1) {
            float t00, t10, t11;
            mat_mul(t00, t10, t11, M00, M10, M11, p00, p10, p11);
            M00 = t00; M10 = t10; M11 = t11;
        }
        mat_sq(p00, p10, p11);
    }
}

// ---------------------------------------------------------------------------
// Pass 1: full pipeline under zero incoming state. Load once, sweep, scan,
// seed, replay+envelope, store. Publish block aggregate for the fixer.
// ---------------------------------------------------------------------------
__global__ void __launch_bounds__(BLOCK, 4)
ng_main(const float* __restrict__ params, const float* __restrict__ x,
        float* __restrict__ out, int n) {
    float c1, c2, at, de, g;
    get_params(params, c1, c2, at, de, g);
    const float b1 = 1.0f - c1;
    const float dcoef = c2 * (c1 - 1.0f);
    const float bb = c2 * b1;

    const int tid = threadIdx.x;
    const int bid = blockIdx.x;
    const int lane = tid & 31, wid = tid >> 5;
    const long base = (long)bid * CHUNK + (long)tid * ITEMS;
    const bool full = (base + ITEMS) <= n;

    // ---- load once, keep in registers ----
    float xv[ITEMS];
    if (full) {
        const float4* xp = (const float4*)(x + base);
        #pragma unroll
        for (int k = 0; k < ITEMS / 4; k++) {
            float4 v = xp[k];
            xv[4*k+0] = v.x; xv[4*k+1] = v.y; xv[4*k+2] = v.z; xv[4*k+3] = v.w;
        }
    } else {
        #pragma unroll
        for (int j = 0; j < ITEMS; j++)
            xv[j] = (base + j < n) ? x[base + j] : 0.0f;
    }

    // ---- stride-4 zero-state sweep ----
    const float A2_00 = c1 * c1, A2_10 = dcoef * (c1 + c2), A2_11 = c2 * c2;
    const float A4_00 = A2_00 * A2_00, A4_10 = A2_10 * (A2_00 + A2_11), A4_11 = A2_11 * A2_11;
    const float q0x = b1,       q0y = bb;
    const float q1x = c1 * q0x, q1y = fmaf(dcoef, q0x, c2 * q0y);
    const float q2x = c1 * q1x, q2y = fmaf(dcoef, q1x, c2 * q1y);
    const float q3x = c1 * q2x, q3y = fmaf(dcoef, q2x, c2 * q2y);

    float v0 = 0.0f, v1 = 0.0f;
    #pragma unroll
    for (int k = 0; k < ITEMS / 4; k++) {
        float xa = xv[4*k+0], xb = xv[4*k+1], xc = xv[4*k+2], xd = xv[4*k+3];
        float u0 = fmaf(q2x, xb, q3x * xa) + fmaf(q0x, xd, q1x * xc);
        float u1 = fmaf(q2y, xb, q3y * xa) + fmaf(q0y, xd, q1y * xc);
        float v0n = fmaf(A4_00, v0, u0);
        v1 = fmaf(A4_10, v0, fmaf(A4_11, v1, u1));
        v0 = v0n;
    }

    // ---- P = A^28; vector-only KS scan; Ml = P^lane ----
    float pk00, pk10, pk11;
    mat_pow28(c1, dcoef, c2, pk00, pk10, pk11);
    float Ml00 = 1.0f, Ml10 = 0.0f, Ml11 = 1.0f;
    #pragma unroll
    for (int k = 0; k < 5; k++) {
        int dd = 1 << k;
        float o0 = __shfl_up_sync(0xffffffffu, v0, dd);
        float o1 = __shfl_up_sync(0xffffffffu, v1, dd);
        if (lane >= dd) {
            v0 = fmaf(pk00, o0, v0);
            v1 = fmaf(pk10, o0, fmaf(pk11, o1, v1));
        }
        if ((lane >> k) & 1) {
            float t00, t10, t11;
            mat_mul(t00, t10, t11, Ml00, Ml10, Ml11, pk00, pk10, pk11);
            Ml00 = t00; Ml10 = t10; Ml11 = t11;
        }
        mat_sq(pk00, pk10, pk11);   // ends: pk = P^32 (warp total)
    }

    float ve0 = __shfl_up_sync(0xffffffffu, v0, 1);
    float ve1 = __shfl_up_sync(0xffffffffu, v1, 1);
    if (lane == 0) { ve0 = 0.0f; ve1 = 0.0f; }

    __shared__ float2 wtotv[NWARP];
    __shared__ float2 prevv[NWARP];
    if (lane == 31) wtotv[wid] = make_float2(v0, v1);
    __syncthreads();
    if (tid == 0) {
        float s0 = 0.0f, s1 = 0.0f;
        #pragma unroll
        for (int w = 0; w < NWARP; w++) {
            prevv[w] = make_float2(s0, s1);
            float2 wv = wtotv[w];
            float ns0 = fmaf(pk00, s0, wv.x);
            s1 = fmaf(pk10, s0, fmaf(pk11, s1, wv.y));
            s0 = ns0;
        }
        g_agg[bid] = make_float2(s0, s1);   // block aggregate (zero-state end)
    }
    __syncthreads();

    // thread's block-local exclusive seed: s = Ml * prevv[wid] + ve
    float2 pv = prevv[wid];
    float y1 = fmaf(Ml00, pv.x, ve0);
    float y2 = fmaf(Ml10, pv.x, fmaf(Ml11, pv.y, ve1));

    // ---- envelope (geometric) ----
    const float inv_n1 = 1.0f / (float)(n - 1);
    const float k1 = 1.0f / de;
    const float k2 = 1.0f / at + k1;
    const float t0 = (float)base * inv_n1;
    float e1 = g * __expf(-t0 * k1);
    float e2 = g * __expf(-t0 * k2);
    const float r1c = __expf(-inv_n1 * k1);
    const float r2c = __expf(-inv_n1 * k2);

    // ---- replay + store (zero-incoming-state output) ----
    if (full) {
        float4* op = (float4*)(out + base);
        #pragma unroll
        for (int k = 0; k < ITEMS / 4; k++) {
            float4 o;
            #pragma unroll
            for (int s = 0; s < 4; s++) {
                float xn = xv[4*k + s];
                float t  = fmaf(dcoef, y1, bb * xn);
                y2 = fmaf(c2, y2, t);
                y1 = fmaf(c1, y1, b1 * xn);
                float val = y2 * (e1 - e2);
                e1 *= r1c; e2 *= r2c;
                if (s == 0) o.x = val; else if (s == 1) o.y = val;
                else if (s == 2) o.z = val; else o.w = val;
            }
            op[k] = o;
        }
    } else if (base < n) {
        #pragma unroll
        for (int j = 0; j < ITEMS; j++) {
            long idx = base + j;
            float xn = xv[j];
            float t  = fmaf(dcoef, y1, bb * xn);
            y2 = fmaf(c2, y2, t);
            y1 = fmaf(c1, y1, b1 * xn);
            float val = y2 * (e1 - e2);
            e1 *= r1c; e2 *= r2c;
            if (idx < n) out[idx] = val;
        }
    }
}

// ---------------------------------------------------------------------------
// Pass 2 (fixer): block bid handles original block b = bid+1. Lookback over
// aggregates -> s_in; correct first FIXN samples: out[j] += env(j) *
// [A^(j+1) s_in].y, with cs iterated cs <- A*cs (no x needed).
// ---------------------------------------------------------------------------
__global__ void __launch_bounds__(FBLOCK, 8)
ng_fix(const float* __restrict__ params, float* __restrict__ out, int n) {
    float c1, c2, at, de, g;
    get_params(params, c1, c2, at, de, g);
    const float dcoef = c2 * (c1 - 1.0f);

    const int tid = threadIdx.x;
    const int b = blockIdx.x + 1;            // original block index (block 0 needs no fix)
    const int lane = tid & 31, wid = tid >> 5;

    // ---- A_C = A^CHUNK = (A^28)^256 ----
    float p00, p10, p11;
    mat_pow28(c1, dcoef, c2, p00, p10, p11);
    #pragma unroll
    for (int k = 0; k < 8; k++) mat_sq(p00, p10, p11);

    // Ml = A_C^tid (tid < 192 -> 8 bits); capture A_C^64, A_C^128 for S = A_C^192
    float Ml00 = 1.0f, Ml10 = 0.0f, Ml11 = 1.0f;
    float C600 = 1.f, C610 = 0.f, C611 = 1.f;
    float C700 = 1.f, C710 = 0.f, C711 = 1.f;
    #pragma unroll
    for (int bb2 = 0; bb2 < 8; bb2++) {
        if (bb2 == 6) { C600 = p00; C610 = p10; C611 = p11; }
        if (bb2 == 7) { C700 = p00; C710 = p10; C711 = p11; }
        if ((tid >> bb2) & 1) {
            float t00, t10, t11;
            mat_mul(t00, t10, t11, Ml00, Ml10, Ml11, p00, p10, p11);
            Ml00 = t00; Ml10 = t10; Ml11 = t11;
        }
        mat_sq(p00, p10, p11);
    }
    float S00, S10, S11;
    mat_mul(S00, S10, S11, C600, C610, C611, C700, C710, C711);   // A_C^192

    // ---- lookback: s_in = sum_{d<b} A_C^d * agg[b-1-d] ----
    float r0 = 0.0f, r1 = 0.0f;
    for (int d = tid; d < b; d += FBLOCK) {
        float2 v = __ldg(&g_agg[b - 1 - d]);
        r0 = fmaf(Ml00, v.x, r0);
        r1 = fmaf(Ml10, v.x, fmaf(Ml11, v.y, r1));
        float t00, t10, t11;
        mat_mul(t00, t10, t11, Ml00, Ml10, Ml11, S00, S10, S11);
        Ml00 = t00; Ml10 = t10; Ml11 = t11;
    }
    #pragma unroll
    for (int d = 16; d > 0; d >>= 1) {
        r0 += __shfl_xor_sync(0xffffffffu, r0, d);
        r1 += __shfl_xor_sync(0xffffffffu, r1, d);
    }
    __shared__ float2 wred[FNWARP];
    if (lane == 0) wred[wid] = make_float2(r0, r1);
    __syncthreads();
    float sx = 0.0f, sy = 0.0f;
    #pragma unroll
    for (int w = 0; w < FNWARP; w++) { sx += wred[w].x; sy += wred[w].y; }

    // ---- correction seed: cs = A^(8*tid+1) * s_in ----
    // A8 = A^8 (3 squarings); M8t = (A8)^tid; cs = A * M8t * s_in
    float a800 = c1, a810 = dcoef, a811 = c2;
    #pragma unroll
    for (int k = 0; k < 3; k++) mat_sq(a800, a810, a811);
    float M00 = 1.0f, M10 = 0.0f, M11 = 1.0f;
    {
        float q00 = a800, q10 = a810, q11 = a811;
        #pragma unroll
        for (int k = 0; k < 8; k++) {
            if ((tid >> k) & 1) {
                float t00, t10, t11;
                mat_mul(t00, t10, t11, M00, M10, M11, q00, q10, q11);
                M00 = t00; M10 = t10; M11 = t11;
            }
            mat_sq(q00, q10, q11);
        }
    }
    float w0 = fmaf(M00, sx, 0.0f);
    float w1 = fmaf(M10, sx, M11 * sy);
    // apply one A: cs = A * w
    float cs0 = c1 * w0;
    float cs1 = fmaf(dcoef, w0, c2 * w1);

    // ---- apply correction to out[gbase .. gbase+8) ----
    const long gbase = (long)b * CHUNK + (long)tid * FITEMS;
    const float inv_n1 = 1.0f / (float)(n - 1);
    const float k1 = 1.0f / de;
    const float k2 = 1.0f / at + k1;
    const float t0 = (float)gbase * inv_n1;
    float e1 = g * __expf(-t0 * k1);
    float e2 = g * __expf(-t0 * k2);
    const float r1c = __expf(-inv_n1 * k1);
    const float r2c = __expf(-inv_n1 * k2);

    if (gbase + FITEMS <= n) {
        float4* op = (float4*)(out + gbase);
        float4 o0 = op[0], o1v = op[1];
        float vals[8] = {o0.x, o0.y, o0.z, o0.w, o1v.x, o1v.y, o1v.z, o1v.w};
        #pragma unroll
        for (int j = 0; j < FITEMS; j++) {
            vals[j] = fmaf(e1 - e2, cs1, vals[j]);
            e1 *= r1c; e2 *= r2c;
            float ncs0 = c1 * cs0;
            cs1 = fmaf(dcoef, cs0, c2 * cs1);
            cs0 = ncs0;
        }
        o0.x = vals[0]; o0.y = vals[1]; o0.z = vals[2]; o0.w = vals[3];
        o1v.x = vals[4]; o1v.y = vals[5]; o1v.z = vals[6]; o1v.w = vals[7];
        op[0] = o0; op[1] = o1v;
    } else if (gbase < n) {
        #pragma unroll
        for (int j = 0; j < FITEMS; j++) {
            long idx = gbase + j;
            if (idx < n) {
                out[idx] = fmaf(e1 - e2, cs1, out[idx]);
            }
            e1 *= r1c; e2 *= r2c;
            float ncs0 = c1 * cs0;
            cs1 = fmaf(dcoef, cs0, c2 * cs1);
            cs0 = ncs0;
        }
    }
}

// ---------------------------------------------------------------------------
extern "C" void kernel_launch(void* const* d_in, const int* in_sizes, int n_in,
                              void* d_out, int out_size) {
    int i_par = 0, i_noise = 1;
    if (n_in >= 2 && in_sizes[0] > in_sizes[1]) { i_par = 1; i_noise = 0; }
    const float* params = (const float*)d_in[i_par];
    const float* noise  = (const float*)d_in[i_noise];
    float* out = (float*)d_out;
    const int n = in_sizes[i_noise];
    int G = (n + CHUNK - 1) / CHUNK;
    if (G > MAXBLKS) G = MAXBLKS;  // n = 2^22 -> G = 586

    ng_main<<<G, BLOCK>>>(params, noise, out, n);
    if (G > 1) ng_fix<<<G - 1, FBLOCK>>>(params, out, n);
}

// round 14
// speedup vs baseline: 1.8099x; 1.1555x over previous
#include <cuda_runtime.h>

#define ITEMS 28
#define BLOCK 256
#define CHUNK (ITEMS * BLOCK)    // 7168 -> G=586
#define NWARP (BLOCK / 32)       // 8
#define MAXBLKS 1024

// correction kernel geometry
#define FIXN   1536              // correct first 1536 samples of each block (0.99^1536 ~ 2e-7)
#define FITEMS 8
#define FBLOCK (FIXN / FITEMS)   // 192 threads

__device__ float2 g_agg[MAXBLKS];   // per-block zero-state end state

__device__ __forceinline__ void get_params(const float* __restrict__ p,
                                           float& c1, float& c2,
                                           float& attack, float& decay, float& gain) {
    attack = fmaxf(p[0], 1e-7f);
    decay  = fmaxf(p[1], 1e-7f);
    c1 = fminf(fmaxf(p[2], 1e-7f), 0.99f);   // lowpass
    c2 = fminf(fmaxf(p[3], 1e-7f), 0.99f);   // highpass
    gain = fmaxf(p[4], 1e-7f);
}

__device__ __forceinline__ void mat_mul(float& c00, float& c10, float& c11,
                                        float a00, float a10, float a11,
                                        float b00, float b10, float b11) {
    c00 = a00 * b00;
    c10 = fmaf(a10, b00, a11 * b10);
    c11 = a11 * b11;
}

__device__ __forceinline__ void mat_sq(float& m00, float& m10, float& m11) {
    float n00 = m00 * m00;
    float n10 = m10 * (m00 + m11);
    float n11 = m11 * m11;
    m00 = n00; m10 = n10; m11 = n11;
}

// P = A^28 (binary 11100): 5 squarings + 3 muls
__device__ __forceinline__ void mat_pow28(float a00, float a10, float a11,
                                          float& M00, float& M10, float& M11) {
    M00 = 1.0f; M10 = 0.0f; M11 = 1.0f;
    float p00 = a00, p10 = a10, p11 = a11;
    #pragma unroll
    for (int b = 0; b < 5; b++) {
        if ((28 >> b) & 1) {
            float t00, t10, t11;
            mat_mul(t00, t10, t11, M00, M10, M11, p00, p10, p11);
            M00 = t00; M10 = t10; M11 = t11;
        }
        mat_sq(p00, p10, p11);
    }
}

// ---------------------------------------------------------------------------
// Pass 1: full pipeline under zero incoming state. Load once, sweep, scan,
// seed, replay+envelope, store. Publish block aggregate for the fixer.
// ---------------------------------------------------------------------------
__global__ void __launch_bounds__(BLOCK, 4)
ng_main(const float* __restrict__ params, const float* __restrict__ x,
        float* __restrict__ out, int n) {
    float c1, c2, at, de, g;
    get_params(params, c1, c2, at, de, g);
    const float b1 = 1.0f - c1;
    const float dcoef = c2 * (c1 - 1.0f);
    const float bb = c2 * b1;

    const int tid = threadIdx.x;
    const int bid = blockIdx.x;
    const int lane = tid & 31, wid = tid >> 5;
    const long base = (long)bid * CHUNK + (long)tid * ITEMS;
    const bool full = (base + ITEMS) <= n;

    // ---- load once, keep in registers ----
    float xv[ITEMS];
    if (full) {
        const float4* xp = (const float4*)(x + base);
        #pragma unroll
        for (int k = 0; k < ITEMS / 4; k++) {
            float4 v = xp[k];
            xv[4*k+0] = v.x; xv[4*k+1] = v.y; xv[4*k+2] = v.z; xv[4*k+3] = v.w;
        }
    } else {
        #pragma unroll
        for (int j = 0; j < ITEMS; j++)
            xv[j] = (base + j < n) ? x[base + j] : 0.0f;
    }

    // ---- stride-4 zero-state sweep ----
    const float A2_00 = c1 * c1, A2_10 = dcoef * (c1 + c2), A2_11 = c2 * c2;
    const float A4_00 = A2_00 * A2_00, A4_10 = A2_10 * (A2_00 + A2_11), A4_11 = A2_11 * A2_11;
    const float q0x = b1,       q0y = bb;
    const float q1x = c1 * q0x, q1y = fmaf(dcoef, q0x, c2 * q0y);
    const float q2x = c1 * q1x, q2y = fmaf(dcoef, q1x, c2 * q1y);
    const float q3x = c1 * q2x, q3y = fmaf(dcoef, q2x, c2 * q2y);

    float v0 = 0.0f, v1 = 0.0f;
    #pragma unroll
    for (int k = 0; k < ITEMS / 4; k++) {
        float xa = xv[4*k+0], xb = xv[4*k+1], xc = xv[4*k+2], xd = xv[4*k+3];
        float u0 = fmaf(q2x, xb, q3x * xa) + fmaf(q0x, xd, q1x * xc);
        float u1 = fmaf(q2y, xb, q3y * xa) + fmaf(q0y, xd, q1y * xc);
        float v0n = fmaf(A4_00, v0, u0);
        v1 = fmaf(A4_10, v0, fmaf(A4_11, v1, u1));
        v0 = v0n;
    }

    // ---- P = A^28; vector-only KS scan; Ml = P^lane ----
    float pk00, pk10, pk11;
    mat_pow28(c1, dcoef, c2, pk00, pk10, pk11);
    float Ml00 = 1.0f, Ml10 = 0.0f, Ml11 = 1.0f;
    #pragma unroll
    for (int k = 0; k < 5; k++) {
        int dd = 1 << k;
        float o0 = __shfl_up_sync(0xffffffffu, v0, dd);
        float o1 = __shfl_up_sync(0xffffffffu, v1, dd);
        if (lane >= dd) {
            v0 = fmaf(pk00, o0, v0);
            v1 = fmaf(pk10, o0, fmaf(pk11, o1, v1));
        }
        if ((lane >> k) & 1) {
            float t00, t10, t11;
            mat_mul(t00, t10, t11, Ml00, Ml10, Ml11, pk00, pk10, pk11);
            Ml00 = t00; Ml10 = t10; Ml11 = t11;
        }
        mat_sq(pk00, pk10, pk11);   // ends: pk = P^32 (warp total)
    }

    float ve0 = __shfl_up_sync(0xffffffffu, v0, 1);
    float ve1 = __shfl_up_sync(0xffffffffu, v1, 1);
    if (lane == 0) { ve0 = 0.0f; ve1 = 0.0f; }

    __shared__ float2 wtotv[NWARP];
    __shared__ float2 prevv[NWARP];
    if (lane == 31) wtotv[wid] = make_float2(v0, v1);
    __syncthreads();
    if (tid == 0) {
        float s0 = 0.0f, s1 = 0.0f;
        #pragma unroll
        for (int w = 0; w < NWARP; w++) {
            prevv[w] = make_float2(s0, s1);
            float2 wv = wtotv[w];
            float ns0 = fmaf(pk00, s0, wv.x);
            s1 = fmaf(pk10, s0, fmaf(pk11, s1, wv.y));
            s0 = ns0;
        }
        g_agg[bid] = make_float2(s0, s1);   // block aggregate (zero-state end)
    }
    __syncthreads();

    // thread's block-local exclusive seed: s = Ml * prevv[wid] + ve
    float2 pv = prevv[wid];
    float y1 = fmaf(Ml00, pv.x, ve0);
    float y2 = fmaf(Ml10, pv.x, fmaf(Ml11, pv.y, ve1));

    // ---- envelope (geometric) ----
    const float inv_n1 = 1.0f / (float)(n - 1);
    const float k1 = 1.0f / de;
    const float k2 = 1.0f / at + k1;
    const float t0 = (float)base * inv_n1;
    float e1 = g * __expf(-t0 * k1);
    float e2 = g * __expf(-t0 * k2);
    const float r1c = __expf(-inv_n1 * k1);
    const float r2c = __expf(-inv_n1 * k2);

    // ---- replay + store (zero-incoming-state output) ----
    if (full) {
        float4* op = (float4*)(out + base);
        #pragma unroll
        for (int k = 0; k < ITEMS / 4; k++) {
            float4 o;
            #pragma unroll
            for (int s = 0; s < 4; s++) {
                float xn = xv[4*k + s];
                float t  = fmaf(dcoef, y1, bb * xn);
                y2 = fmaf(c2, y2, t);
                y1 = fmaf(c1, y1, b1 * xn);
                float val = y2 * (e1 - e2);
                e1 *= r1c; e2 *= r2c;
                if (s == 0) o.x = val; else if (s == 1) o.y = val;
                else if (s == 2) o.z = val; else o.w = val;
            }
            op[k] = o;
        }
    } else if (base < n) {
        #pragma unroll
        for (int j = 0; j < ITEMS; j++) {
            long idx = base + j;
            float xn = xv[j];
            float t  = fmaf(dcoef, y1, bb * xn);
            y2 = fmaf(c2, y2, t);
            y1 = fmaf(c1, y1, b1 * xn);
            float val = y2 * (e1 - e2);
            e1 *= r1c; e2 *= r2c;
            if (idx < n) out[idx] = val;
        }
    }
}

// ---------------------------------------------------------------------------
// Pass 2 (fixer): s_in(b) = agg[b-1] EXACTLY in fp32 (A^7168 ~ 5e-32 -> all
// further lookback terms flush to zero). No lookback, no reductions, no
// barriers: one load, binary power, 8-sample RMW.
// ---------------------------------------------------------------------------
__global__ void __launch_bounds__(FBLOCK, 8)
ng_fix(const float* __restrict__ params, float* __restrict__ out, int n) {
    float c1, c2, at, de, g;
    get_params(params, c1, c2, at, de, g);
    const float dcoef = c2 * (c1 - 1.0f);

    const int tid = threadIdx.x;
    const int b = blockIdx.x + 1;            // original block index (block 0 needs no fix)

    // ---- incoming state: single load ----
    float2 sin2 = __ldg(&g_agg[b - 1]);

    // ---- cs = A^(8*tid+1) * s_in : A8 = A^8 (3 squarings), (A8)^tid, then *A ----
    float a800 = c1, a810 = dcoef, a811 = c2;
    #pragma unroll
    for (int k = 0; k < 3; k++) mat_sq(a800, a810, a811);
    float M00 = 1.0f, M10 = 0.0f, M11 = 1.0f;
    {
        float q00 = a800, q10 = a810, q11 = a811;
        #pragma unroll
        for (int k = 0; k < 8; k++) {
            if ((tid >> k) & 1) {
                float t00, t10, t11;
                mat_mul(t00, t10, t11, M00, M10, M11, q00, q10, q11);
                M00 = t00; M10 = t10; M11 = t11;
            }
            mat_sq(q00, q10, q11);
        }
    }
    float w0 = M00 * sin2.x;
    float w1 = fmaf(M10, sin2.x, M11 * sin2.y);
    float cs0 = c1 * w0;
    float cs1 = fmaf(dcoef, w0, c2 * w1);

    // ---- apply correction to out[gbase .. gbase+8) ----
    const long gbase = (long)b * CHUNK + (long)tid * FITEMS;
    const float inv_n1 = 1.0f / (float)(n - 1);
    const float k1 = 1.0f / de;
    const float k2 = 1.0f / at + k1;
    const float t0 = (float)gbase * inv_n1;
    float e1 = g * __expf(-t0 * k1);
    float e2 = g * __expf(-t0 * k2);
    const float r1c = __expf(-inv_n1 * k1);
    const float r2c = __expf(-inv_n1 * k2);

    if (gbase + FITEMS <= n) {
        float4* op = (float4*)(out + gbase);
        float4 o0 = op[0], o1v = op[1];
        float vals[8] = {o0.x, o0.y, o0.z, o0.w, o1v.x, o1v.y, o1v.z, o1v.w};
        #pragma unroll
        for (int j = 0; j < FITEMS; j++) {
            vals[j] = fmaf(e1 - e2, cs1, vals[j]);
            e1 *= r1c; e2 *= r2c;
            float ncs0 = c1 * cs0;
            cs1 = fmaf(dcoef, cs0, c2 * cs1);
            cs0 = ncs0;
        }
        o0.x = vals[0]; o0.y = vals[1]; o0.z = vals[2]; o0.w = vals[3];
        o1v.x = vals[4]; o1v.y = vals[5]; o1v.z = vals[6]; o1v.w = vals[7];
        op[0] = o0; op[1] = o1v;
    } else if (gbase < n) {
        #pragma unroll
        for (int j = 0; j < FITEMS; j++) {
            long idx = gbase + j;
            if (idx < n) {
                out[idx] = fmaf(e1 - e2, cs1, out[idx]);
            }
            e1 *= r1c; e2 *= r2c;
            float ncs0 = c1 * cs0;
            cs1 = fmaf(dcoef, cs0, c2 * cs1);
            cs0 = ncs0;
        }
    }
}

// ---------------------------------------------------------------------------
extern "C" void kernel_launch(void* const* d_in, const int* in_sizes, int n_in,
                              void* d_out, int out_size) {
    int i_par = 0, i_noise = 1;
    if (n_in >= 2 && in_sizes[0] > in_sizes[1]) { i_par = 1; i_noise = 0; }
    const float* params = (const float*)d_in[i_par];
    const float* noise  = (const float*)d_in[i_noise];
    float* out = (float*)d_out;
    const int n = in_sizes[i_noise];
    int G = (n + CHUNK - 1) / CHUNK;
    if (G > MAXBLKS) G = MAXBLKS;  // n = 2^22 -> G = 586

    ng_main<<<G, BLOCK>>>(params, noise, out, n);
    if (G > 1) ng_fix<<<G - 1, FBLOCK>>>(params, out, n);
}